// round 1
// baseline (speedup 1.0000x reference)
#include <cuda_runtime.h>
#include <math.h>

#define T_ 4
#define B_ 16
#define C_ 256
#define L_ 2048
#define O_ 512
#define TBCL_ (T_*B_*C_*L_)

// z in {0, ZA, ZB}: ZA = 0.5*tanh(1), ZB = sigmoid(1)*tanh(1)
#define ZA 0.38079708f
#define ZB 0.55676994f

// Scratch (device globals: no allocation allowed in kernel_launch)
__device__ float g_z[TBCL_];          // 128 MB: z[t][b][c][l]
__device__ float g_proj[B_*C_];
__device__ float g_base[B_*O_];       // conv(proj) full + b_conv
__device__ float g_e0[B_*O_];         // k=0 partial (subtract at l=0)
__device__ float g_e2[B_*O_];         // k=2 partial (subtract at l=L-1)
__device__ float g_wc[3*C_*O_];       // conv weights transposed: [k][c][o]
__device__ float g_wn[C_*O_];         // [c][n] n<256: w_res, else w_skip

// ---------------- prep: proj[b][c] ----------------
__global__ void k_proj(const int* __restrict__ dstep,
                       const float* __restrict__ w1, const float* __restrict__ b1,
                       const float* __restrict__ w2, const float* __restrict__ b2,
                       const float* __restrict__ wp, const float* __restrict__ bp) {
    int b = blockIdx.x;
    int c = threadIdx.x;
    __shared__ float h[C_];
    __shared__ float emb[C_];
    float ds = (float)dstep[b];
    float t1 = ds * w1[c] + b1[c];
    float s = 1.f / (1.f + expf(-t1));
    h[c] = t1 * s;                       // silu
    __syncthreads();
    float e = b2[c];
    const float* w2r = w2 + c * C_;
    for (int j = 0; j < C_; j++) e += w2r[j] * h[j];
    __syncthreads();
    emb[c] = e;
    __syncthreads();
    float p = bp[c];
    const float* wpr = wp + c * C_;
    for (int j = 0; j < C_; j++) p += wpr[j] * emb[j];
    g_proj[b * C_ + c] = p;
}

// ---------------- prep: weight transposes ----------------
__global__ void k_wtrans(const float* __restrict__ w_conv,
                         const float* __restrict__ w_skip,
                         const float* __restrict__ w_res) {
    int i = blockIdx.x * 256 + threadIdx.x;
    if (i < 3 * C_ * O_) {
        int o = i % O_;
        int c = (i / O_) % C_;
        int k = i / (O_ * C_);
        g_wc[i] = w_conv[(o * C_ + c) * 3 + k];
    }
    if (i < C_ * O_) {
        int n = i % O_;
        int c = i / O_;
        g_wn[i] = (n < C_) ? w_res[n * C_ + c] : w_skip[(n - C_) * C_ + c];
    }
}

// ---------------- prep: conv(proj) per (b,o) + edges ----------------
__global__ void k_econv(const float* __restrict__ b_conv) {
    int b = blockIdx.x;
    int o = blockIdx.y * 128 + threadIdx.x;
    __shared__ float pr[C_];
    for (int i = threadIdx.x; i < C_; i += 128) pr[i] = g_proj[b * C_ + i];
    __syncthreads();
    float e0 = 0.f, e1 = 0.f, e2 = 0.f;
    for (int c = 0; c < C_; c++) {
        float p = pr[c];
        e0 += g_wc[(0 * C_ + c) * O_ + o] * p;
        e1 += g_wc[(1 * C_ + c) * O_ + o] * p;
        e2 += g_wc[(2 * C_ + c) * O_ + o] * p;
    }
    g_base[b * O_ + o] = e0 + e1 + e2 + b_conv[o];
    g_e0[b * O_ + o] = e0;
    g_e2[b * O_ + o] = e2;
}

// ---------------- conv1d + LIF + z (fused over T) ----------------
// grid: (L/64, 4 o-pair-tiles, B), block 256
// block tile: 64 l positions x 128 o-cols = 64 (gate,filt) channel pairs
__global__ void __launch_bounds__(256, 2) k_conv_lif(const float* __restrict__ x) {
    const int l0 = blockIdx.x * 64;
    const int ot = blockIdx.y;            // channel-pair tile: pairs [ot*64, ot*64+64)
    const int b  = blockIdx.z;
    const int tid = threadIdx.x;
    const int tx = tid & 15;              // row group: 4 l's
    const int ty = tid >> 4;              // col group: 4 pairs
    const int r0 = tx * 4;

    __shared__ float xs[16][66];          // 16 c x (64+2 halo) l
    __shared__ float ws[16][3][128];      // 16 c x 3 k x 128 cols

    float v[2][4][4];                     // [gate/filt][pair q][l]
    #pragma unroll
    for (int h = 0; h < 2; h++)
        #pragma unroll
        for (int q = 0; q < 4; q++)
            #pragma unroll
            for (int li = 0; li < 4; li++) v[h][q][li] = 0.f;

    #pragma unroll 1
    for (int t = 0; t < T_; t++) {
        float acc[2][4][4];
        #pragma unroll
        for (int h = 0; h < 2; h++)
            #pragma unroll
            for (int q = 0; q < 4; q++)
                #pragma unroll
                for (int li = 0; li < 4; li++) acc[h][q][li] = 0.f;

        const float* xb = x + (size_t)((t * B_ + b) * C_) * L_;

        #pragma unroll 1
        for (int cc = 0; cc < C_; cc += 16) {
            // load x tile (with zero-padded halo)
            for (int i = tid; i < 16 * 66; i += 256) {
                int ci = i / 66, li = i % 66;
                int gl = l0 - 1 + li;
                float val = 0.f;
                if (gl >= 0 && gl < L_) val = xb[(cc + ci) * L_ + gl];
                xs[ci][li] = val;
            }
            // load weight tile (coalesced from transposed g_wc)
            for (int i = tid; i < 6144; i += 256) {
                int col = i & 127;
                int k = (i >> 7) % 3;
                int ci = i / 384;
                int o = (col < 64) ? (ot * 64 + col) : (256 + ot * 64 + (col - 64));
                ws[ci][k][col] = g_wc[(k * C_ + cc + ci) * O_ + o];
            }
            __syncthreads();

            #pragma unroll
            for (int ci = 0; ci < 16; ci++) {
                float xr[6];
                #pragma unroll
                for (int s = 0; s < 6; s++) xr[s] = xs[ci][r0 + s];
                #pragma unroll
                for (int q = 0; q < 4; q++) {
                    int cA = ty * 4 + q;
                    float wA0 = ws[ci][0][cA], wA1 = ws[ci][1][cA], wA2 = ws[ci][2][cA];
                    float wB0 = ws[ci][0][cA + 64], wB1 = ws[ci][1][cA + 64], wB2 = ws[ci][2][cA + 64];
                    #pragma unroll
                    for (int li = 0; li < 4; li++) {
                        float x0 = xr[li], x1 = xr[li + 1], x2 = xr[li + 2];
                        acc[0][q][li] += wA0 * x0 + wA1 * x1 + wA2 * x2;
                        acc[1][q][li] += wB0 * x0 + wB1 * x1 + wB2 * x2;
                    }
                }
            }
            __syncthreads();
        }

        // epilogue: add conv(proj)+bias (w/ edge fix), LIF step, z, store
        float* zb = g_z + (size_t)((t * B_ + b) * C_) * L_;
        #pragma unroll
        for (int q = 0; q < 4; q++) {
            int og = ot * 64 + ty * 4 + q;     // gate channel == z channel
            int of = og + 256;                 // filt channel
            float baseg = g_base[b * O_ + og], basef = g_base[b * O_ + of];
            float e0g = g_e0[b * O_ + og], e0f = g_e0[b * O_ + of];
            float e2g = g_e2[b * O_ + og], e2f = g_e2[b * O_ + of];
            float4 zq;
            float* zqp = (float*)&zq;
            #pragma unroll
            for (int li = 0; li < 4; li++) {
                int gl = l0 + r0 + li;
                float bg = baseg, bf = basef;
                if (gl == 0)      { bg -= e0g; bf -= e0f; }
                if (gl == L_ - 1) { bg -= e2g; bf -= e2f; }
                float yg = acc[0][q][li] + bg;
                float yf = acc[1][q][li] + bf;
                float vg = v[0][q][li]; vg = vg + (yg - vg) / 1.2f;
                float vf = v[1][q][li]; vf = vf + (yf - vf) / 1.2f;
                bool sg = vg >= 0.5f;
                bool sf = vf >= 0.5f;
                v[0][q][li] = sg ? 0.f : vg;
                v[1][q][li] = sf ? 0.f : vf;
                zqp[li] = sf ? (sg ? ZB : ZA) : 0.f;
            }
            *(float4*)(zb + (size_t)og * L_ + l0 + r0) = zq;
        }
    }
}

// ---------------- output GEMM: [x+res ; skip] ----------------
// grid: (L/64, 4 n-tiles, T*B), block 256
__global__ void __launch_bounds__(256, 2) k_out(const float* __restrict__ x,
                                                const float* __restrict__ b_skip,
                                                const float* __restrict__ b_res,
                                                float* __restrict__ out) {
    const int l0 = blockIdx.x * 64;
    const int nb = blockIdx.y * 128;
    const int t = blockIdx.z >> 4;
    const int b = blockIdx.z & 15;
    const int tid = threadIdx.x;
    const int tx = tid & 15;              // 4 rows (l)
    const int ty = tid >> 4;              // 8 cols (n)

    __shared__ float zs[16][64];
    __shared__ float wn[16][128];

    float acc[8][4];
    #pragma unroll
    for (int j = 0; j < 8; j++)
        #pragma unroll
        for (int li = 0; li < 4; li++) acc[j][li] = 0.f;

    const float* zb = g_z + (size_t)((t * B_ + b) * C_) * L_;

    #pragma unroll 1
    for (int cc = 0; cc < C_; cc += 16) {
        {   // z tile: 1024 floats, one float4 per thread
            int ci = tid >> 4;
            int l4 = tid & 15;
            *(float4*)&zs[ci][l4 * 4] =
                *(const float4*)(zb + (cc + ci) * L_ + l0 + l4 * 4);
        }
        #pragma unroll
        for (int r = 0; r < 2; r++) {     // w tile: 2048 floats, 2 float4/thread
            int idx = tid + r * 256;      // 0..511
            int j4 = idx & 31;
            int ci = idx >> 5;
            *(float4*)&wn[ci][j4 * 4] =
                *(const float4*)(&g_wn[(cc + ci) * O_ + nb + j4 * 4]);
        }
        __syncthreads();

        #pragma unroll
        for (int ci = 0; ci < 16; ci++) {
            float4 zr = *(float4*)&zs[ci][tx * 4];
            float4 w0 = *(float4*)&wn[ci][ty * 8];
            float4 w1 = *(float4*)&wn[ci][ty * 8 + 4];
            float wr[8] = {w0.x, w0.y, w0.z, w0.w, w1.x, w1.y, w1.z, w1.w};
            float zl[4] = {zr.x, zr.y, zr.z, zr.w};
            #pragma unroll
            for (int j = 0; j < 8; j++)
                #pragma unroll
                for (int li = 0; li < 4; li++) acc[j][li] += wr[j] * zl[li];
        }
        __syncthreads();
    }

    #pragma unroll
    for (int j = 0; j < 8; j++) {
        int n = nb + ty * 8 + j;
        bool isres = (n < C_);
        int o = isres ? n : (n - C_);
        size_t idx = ((size_t)(t * B_ + b) * C_ + o) * L_ + l0 + tx * 4;
        float bias = isres ? b_res[o] : b_skip[o];
        float4 r;
        if (isres) {
            float4 xv = *(const float4*)(x + idx);
            r.x = acc[j][0] + xv.x + bias;
            r.y = acc[j][1] + xv.y + bias;
            r.z = acc[j][2] + xv.z + bias;
            r.w = acc[j][3] + xv.w + bias;
            *(float4*)(out + idx) = r;
        } else {
            r.x = acc[j][0] + bias;
            r.y = acc[j][1] + bias;
            r.z = acc[j][2] + bias;
            r.w = acc[j][3] + bias;
            *(float4*)(out + TBCL_ + idx) = r;
        }
    }
}

extern "C" void kernel_launch(void* const* d_in, const int* in_sizes, int n_in,
                              void* d_out, int out_size) {
    const float* x      = (const float*)d_in[0];
    const int*   dstep  = (const int*)d_in[1];
    const float* w_emb1 = (const float*)d_in[2];
    const float* b_emb1 = (const float*)d_in[3];
    const float* w_emb2 = (const float*)d_in[4];
    const float* b_emb2 = (const float*)d_in[5];
    const float* w_proj = (const float*)d_in[6];
    const float* b_proj = (const float*)d_in[7];
    const float* w_conv = (const float*)d_in[8];
    const float* b_conv = (const float*)d_in[9];
    const float* w_skip = (const float*)d_in[10];
    const float* b_skip = (const float*)d_in[11];
    const float* w_res  = (const float*)d_in[12];
    const float* b_res  = (const float*)d_in[13];
    float* out = (float*)d_out;

    k_proj<<<B_, C_>>>(dstep, w_emb1, b_emb1, w_emb2, b_emb2, w_proj, b_proj);
    k_wtrans<<<(3 * C_ * O_ + 255) / 256, 256>>>(w_conv, w_skip, w_res);
    k_econv<<<dim3(B_, O_ / 128), 128>>>(b_conv);
    k_conv_lif<<<dim3(L_ / 64, 4, B_), 256>>>(x);
    k_out<<<dim3(L_ / 64, 4, T_ * B_), 256>>>(x, b_skip, b_res, out);
}

// round 2
// speedup vs baseline: 1.3562x; 1.3562x over previous
#include <cuda_runtime.h>
#include <math.h>

#define T_ 4
#define B_ 16
#define C_ 256
#define L_ 2048
#define O_ 512
#define TBCL_ (T_*B_*C_*L_)

// z in {0, ZA, ZB}: ZA = 0.5*tanh(1), ZB = sigmoid(1)*tanh(1)
#define ZA 0.38079708f
#define ZB 0.55676994f

typedef unsigned long long u64;

__device__ __forceinline__ u64 pack2(float lo, float hi) {
    u64 d; asm("mov.b64 %0, {%1, %2};" : "=l"(d) : "f"(lo), "f"(hi)); return d;
}
__device__ __forceinline__ void unpack2(u64 v, float& lo, float& hi) {
    asm("mov.b64 {%0, %1}, %2;" : "=f"(lo), "=f"(hi) : "l"(v));
}
__device__ __forceinline__ u64 fma2(u64 a, u64 b, u64 c) {
    u64 d; asm("fma.rn.f32x2 %0, %1, %2, %3;" : "=l"(d) : "l"(a), "l"(b), "l"(c)); return d;
}

// Scratch (device globals: no allocation allowed in kernel_launch)
__device__ float g_z[TBCL_];          // 128 MB: z[t][b][c][l]
__device__ float g_proj[B_*C_];
__device__ float g_base[B_*O_];       // conv(proj) full + b_conv
__device__ float g_e0[B_*O_];         // k=0 partial (subtract at l=0)
__device__ float g_e2[B_*O_];         // k=2 partial (subtract at l=L-1)
__device__ float g_wc[3*C_*O_];       // conv weights transposed: [k][c][o]
__device__ float g_wn[C_*O_];         // [c][n] n<256: w_res, else w_skip

// ---------------- prep: proj[b][c] ----------------
__global__ void k_proj(const int* __restrict__ dstep,
                       const float* __restrict__ w1, const float* __restrict__ b1,
                       const float* __restrict__ w2, const float* __restrict__ b2,
                       const float* __restrict__ wp, const float* __restrict__ bp) {
    int b = blockIdx.x;
    int c = threadIdx.x;
    __shared__ float h[C_];
    __shared__ float emb[C_];
    float ds = (float)dstep[b];
    float t1 = ds * w1[c] + b1[c];
    float s = 1.f / (1.f + expf(-t1));
    h[c] = t1 * s;                       // silu
    __syncthreads();
    float e = b2[c];
    const float* w2r = w2 + c * C_;
    for (int j = 0; j < C_; j++) e += w2r[j] * h[j];
    __syncthreads();
    emb[c] = e;
    __syncthreads();
    float p = bp[c];
    const float* wpr = wp + c * C_;
    for (int j = 0; j < C_; j++) p += wpr[j] * emb[j];
    g_proj[b * C_ + c] = p;
}

// ---------------- prep: weight transposes ----------------
__global__ void k_wtrans(const float* __restrict__ w_conv,
                         const float* __restrict__ w_skip,
                         const float* __restrict__ w_res) {
    int i = blockIdx.x * 256 + threadIdx.x;
    if (i < 3 * C_ * O_) {
        int o = i % O_;
        int c = (i / O_) % C_;
        int k = i / (O_ * C_);
        g_wc[i] = w_conv[(o * C_ + c) * 3 + k];
    }
    if (i < C_ * O_) {
        int n = i % O_;
        int c = i / O_;
        g_wn[i] = (n < C_) ? w_res[n * C_ + c] : w_skip[(n - C_) * C_ + c];
    }
}

// ---------------- prep: conv(proj) per (b,o) + edges ----------------
__global__ void k_econv(const float* __restrict__ b_conv) {
    int b = blockIdx.x;
    int o = blockIdx.y * 128 + threadIdx.x;
    __shared__ float pr[C_];
    for (int i = threadIdx.x; i < C_; i += 128) pr[i] = g_proj[b * C_ + i];
    __syncthreads();
    float e0 = 0.f, e1 = 0.f, e2 = 0.f;
    for (int c = 0; c < C_; c++) {
        float p = pr[c];
        e0 += g_wc[(0 * C_ + c) * O_ + o] * p;
        e1 += g_wc[(1 * C_ + c) * O_ + o] * p;
        e2 += g_wc[(2 * C_ + c) * O_ + o] * p;
    }
    g_base[b * O_ + o] = e0 + e1 + e2 + b_conv[o];
    g_e0[b * O_ + o] = e0;
    g_e2[b * O_ + o] = e2;
}

// ---------------- conv1d + LIF + z (fused over T), packed f32x2 ----------------
// grid: (L/64, 4 pair-tiles, B), block 256
// block tile: 64 l positions x 64 (gate,filt) channel pairs
__global__ void __launch_bounds__(256, 2) k_conv_lif(const float* __restrict__ x) {
    const int l0 = blockIdx.x * 64;
    const int ot = blockIdx.y;            // channel-pair tile: pairs [ot*64, ot*64+64)
    const int b  = blockIdx.z;
    const int tid = threadIdx.x;
    const int tx = tid & 15;              // row group: 4 l's
    const int ty = tid >> 4;              // col group: 4 pairs
    const int r0 = tx * 4;

    __shared__ float  xs[16][66];         // 16 c x (64+2 halo) l
    __shared__ float2 ws[16][3][64];      // 16 c x 3 k x 64 (gate,filt) pairs

    float v[2][4][4];                     // [gate/filt][pair q][l]
    #pragma unroll
    for (int h = 0; h < 2; h++)
        #pragma unroll
        for (int q = 0; q < 4; q++)
            #pragma unroll
            for (int li = 0; li < 4; li++) v[h][q][li] = 0.f;

    #pragma unroll 1
    for (int t = 0; t < T_; t++) {
        u64 acc2[4][4];                   // (gate,filt) packed accumulators
        #pragma unroll
        for (int q = 0; q < 4; q++)
            #pragma unroll
            for (int li = 0; li < 4; li++) acc2[q][li] = 0ull;

        const float* xb = x + (size_t)((t * B_ + b) * C_) * L_;

        #pragma unroll 1
        for (int cc = 0; cc < C_; cc += 16) {
            // load x tile (with zero-padded halo)
            for (int i = tid; i < 16 * 66; i += 256) {
                int ci = i / 66, li = i % 66;
                int gl = l0 - 1 + li;
                float val = 0.f;
                if (gl >= 0 && gl < L_) val = xb[(cc + ci) * L_ + gl];
                xs[ci][li] = val;
            }
            // load weight tile as (gate,filt) pairs (coalesced from g_wc)
            for (int i = tid; i < 3072; i += 256) {
                int p = i & 63;
                int k = (i >> 6) % 3;
                int ci = i / 192;
                int og = ot * 64 + p;
                const float* wrow = &g_wc[(k * C_ + cc + ci) * O_];
                ws[ci][k][p] = make_float2(wrow[og], wrow[og + 256]);
            }
            __syncthreads();

            #pragma unroll
            for (int ci = 0; ci < 16; ci++) {
                u64 xx[6];
                #pragma unroll
                for (int s = 0; s < 6; s++) {
                    float xv = xs[ci][r0 + s];
                    xx[s] = pack2(xv, xv);
                }
                #pragma unroll
                for (int q = 0; q < 4; q++) {
                    int cq = ty * 4 + q;
                    u64 w0 = *(const u64*)&ws[ci][0][cq];
                    u64 w1 = *(const u64*)&ws[ci][1][cq];
                    u64 w2 = *(const u64*)&ws[ci][2][cq];
                    #pragma unroll
                    for (int li = 0; li < 4; li++) {
                        acc2[q][li] = fma2(w0, xx[li],     acc2[q][li]);
                        acc2[q][li] = fma2(w1, xx[li + 1], acc2[q][li]);
                        acc2[q][li] = fma2(w2, xx[li + 2], acc2[q][li]);
                    }
                }
            }
            __syncthreads();
        }

        // epilogue: add conv(proj)+bias (w/ edge fix), LIF step, z, store
        float* zb = g_z + (size_t)((t * B_ + b) * C_) * L_;
        #pragma unroll
        for (int q = 0; q < 4; q++) {
            int og = ot * 64 + ty * 4 + q;     // gate channel == z channel
            int of = og + 256;                 // filt channel
            float baseg = g_base[b * O_ + og], basef = g_base[b * O_ + of];
            float e0g = g_e0[b * O_ + og], e0f = g_e0[b * O_ + of];
            float e2g = g_e2[b * O_ + og], e2f = g_e2[b * O_ + of];
            float4 zq;
            float* zqp = (float*)&zq;
            #pragma unroll
            for (int li = 0; li < 4; li++) {
                int gl = l0 + r0 + li;
                float bg = baseg, bf = basef;
                if (gl == 0)      { bg -= e0g; bf -= e0f; }
                if (gl == L_ - 1) { bg -= e2g; bf -= e2f; }
                float ag, af;
                unpack2(acc2[q][li], ag, af);
                float yg = ag + bg;
                float yf = af + bf;
                float vg = v[0][q][li]; vg = vg + (yg - vg) / 1.2f;
                float vf = v[1][q][li]; vf = vf + (yf - vf) / 1.2f;
                bool sg = vg >= 0.5f;
                bool sf = vf >= 0.5f;
                v[0][q][li] = sg ? 0.f : vg;
                v[1][q][li] = sf ? 0.f : vf;
                zqp[li] = sf ? (sg ? ZB : ZA) : 0.f;
            }
            *(float4*)(zb + (size_t)og * L_ + l0 + r0) = zq;
        }
    }
}

// ---------------- output GEMM: [x+res ; skip], packed f32x2 ----------------
// grid: (L/64, 4 n-tiles, T*B), block 256
__global__ void __launch_bounds__(256, 2) k_out(const float* __restrict__ x,
                                                const float* __restrict__ b_skip,
                                                const float* __restrict__ b_res,
                                                float* __restrict__ out) {
    const int l0 = blockIdx.x * 64;
    const int nb = blockIdx.y * 128;
    const int t = blockIdx.z >> 4;
    const int b = blockIdx.z & 15;
    const int tid = threadIdx.x;
    const int tx = tid & 15;              // 4 rows (l)
    const int ty = tid >> 4;              // 8 cols (n) = 4 pairs

    __shared__ float zs[16][64];
    __shared__ float wn[16][128];

    u64 acc2[4][4];                       // 4 n-pairs x 4 l
    #pragma unroll
    for (int j = 0; j < 4; j++)
        #pragma unroll
        for (int li = 0; li < 4; li++) acc2[j][li] = 0ull;

    const float* zb = g_z + (size_t)((t * B_ + b) * C_) * L_;

    #pragma unroll 1
    for (int cc = 0; cc < C_; cc += 16) {
        {   // z tile: 1024 floats, one float4 per thread
            int ci = tid >> 4;
            int l4 = tid & 15;
            *(float4*)&zs[ci][l4 * 4] =
                *(const float4*)(zb + (cc + ci) * L_ + l0 + l4 * 4);
        }
        #pragma unroll
        for (int r = 0; r < 2; r++) {     // w tile: 2048 floats, 2 float4/thread
            int idx = tid + r * 256;      // 0..511
            int j4 = idx & 31;
            int ci = idx >> 5;
            *(float4*)&wn[ci][j4 * 4] =
                *(const float4*)(&g_wn[(cc + ci) * O_ + nb + j4 * 4]);
        }
        __syncthreads();

        #pragma unroll
        for (int ci = 0; ci < 16; ci++) {
            float4 zr = *(float4*)&zs[ci][tx * 4];
            u64 zz[4];
            zz[0] = pack2(zr.x, zr.x);
            zz[1] = pack2(zr.y, zr.y);
            zz[2] = pack2(zr.z, zr.z);
            zz[3] = pack2(zr.w, zr.w);
            #pragma unroll
            for (int j2 = 0; j2 < 4; j2++) {
                u64 w = *(const u64*)&wn[ci][ty * 8 + j2 * 2];
                #pragma unroll
                for (int li = 0; li < 4; li++)
                    acc2[j2][li] = fma2(w, zz[li], acc2[j2][li]);
            }
        }
        __syncthreads();
    }

    float acc[8][4];
    #pragma unroll
    for (int j2 = 0; j2 < 4; j2++)
        #pragma unroll
        for (int li = 0; li < 4; li++)
            unpack2(acc2[j2][li], acc[2 * j2][li], acc[2 * j2 + 1][li]);

    #pragma unroll
    for (int j = 0; j < 8; j++) {
        int n = nb + ty * 8 + j;
        bool isres = (n < C_);
        int o = isres ? n : (n - C_);
        size_t idx = ((size_t)(t * B_ + b) * C_ + o) * L_ + l0 + tx * 4;
        float bias = isres ? b_res[o] : b_skip[o];
        float4 r;
        if (isres) {
            float4 xv = *(const float4*)(x + idx);
            r.x = acc[j][0] + xv.x + bias;
            r.y = acc[j][1] + xv.y + bias;
            r.z = acc[j][2] + xv.z + bias;
            r.w = acc[j][3] + xv.w + bias;
            *(float4*)(out + idx) = r;
        } else {
            r.x = acc[j][0] + bias;
            r.y = acc[j][1] + bias;
            r.z = acc[j][2] + bias;
            r.w = acc[j][3] + bias;
            *(float4*)(out + TBCL_ + idx) = r;
        }
    }
}

extern "C" void kernel_launch(void* const* d_in, const int* in_sizes, int n_in,
                              void* d_out, int out_size) {
    const float* x      = (const float*)d_in[0];
    const int*   dstep  = (const int*)d_in[1];
    const float* w_emb1 = (const float*)d_in[2];
    const float* b_emb1 = (const float*)d_in[3];
    const float* w_emb2 = (const float*)d_in[4];
    const float* b_emb2 = (const float*)d_in[5];
    const float* w_proj = (const float*)d_in[6];
    const float* b_proj = (const float*)d_in[7];
    const float* w_conv = (const float*)d_in[8];
    const float* b_conv = (const float*)d_in[9];
    const float* w_skip = (const float*)d_in[10];
    const float* b_skip = (const float*)d_in[11];
    const float* w_res  = (const float*)d_in[12];
    const float* b_res  = (const float*)d_in[13];
    float* out = (float*)d_out;

    k_proj<<<B_, C_>>>(dstep, w_emb1, b_emb1, w_emb2, b_emb2, w_proj, b_proj);
    k_wtrans<<<(3 * C_ * O_ + 255) / 256, 256>>>(w_conv, w_skip, w_res);
    k_econv<<<dim3(B_, O_ / 128), 128>>>(b_conv);
    k_conv_lif<<<dim3(L_ / 64, 4, B_), 256>>>(x);
    k_out<<<dim3(L_ / 64, 4, T_ * B_), 256>>>(x, b_skip, b_res, out);
}